// round 1
// baseline (speedup 1.0000x reference)
#include <cuda_runtime.h>
#include <math.h>

#define NB 4
#define NL 1024
#define ND 1024
#define NH 16
#define NHD 64
#define NBH (NB*NH)

// ---- scratch (device globals; no allocation allowed) ----
__device__ __align__(16) float g_pq[NBH*NL*NHD];
__device__ __align__(16) float g_hq[NBH*NL*NHD];
__device__ __align__(16) float g_vq[NBH*NL*NHD];
__device__ __align__(16) float g_k [NBH*NL*NHD];
__device__ __align__(16) float g_v [NBH*NL*NHD];
__device__ __align__(16) float g_cf[NH*NL*NHD];
__device__ __align__(16) float g_bf[NH*NL*NHD];
__device__ __align__(16) float g_ctx[NB*NL*ND];

// ============================================================
// Generic 64x64 SGEMM tile, K=1024, BK=16, 256 thr, 4x4/thread.
// C = A[4096,1024] @ W[1024,1024] + bias
// HEADMAJOR: write C[m, n] to out[((b*16+h)*1024 + l)*64 + hd]
// ============================================================
template<bool HEADMAJOR>
__global__ __launch_bounds__(256) void sgemm_bias(
    const float* __restrict__ A, const float* __restrict__ W,
    const float* __restrict__ bias, float* __restrict__ C)
{
    const int m0 = blockIdx.y * 64;
    const int n0 = blockIdx.x * 64;
    const int tid = threadIdx.x;
    const int tx = tid & 15, ty = tid >> 4;
    __shared__ __align__(16) float As[16][64];
    __shared__ __align__(16) float Ws[16][64];
    float acc[4][4] = {};
    const int lr = tid >> 2, lk = (tid & 3) * 4;   // A tile loader
    const int wk = tid >> 4, wn = (tid & 15) * 4;  // W tile loader

    for (int k0 = 0; k0 < 1024; k0 += 16) {
        float4 av = *(const float4*)(A + (size_t)(m0 + lr) * 1024 + k0 + lk);
        float4 wv = *(const float4*)(W + (size_t)(k0 + wk) * 1024 + n0 + wn);
        __syncthreads();
        As[lk+0][lr] = av.x; As[lk+1][lr] = av.y;
        As[lk+2][lr] = av.z; As[lk+3][lr] = av.w;
        *(float4*)(&Ws[wk][wn]) = wv;
        __syncthreads();
#pragma unroll
        for (int kk = 0; kk < 16; kk++) {
            float4 a = *(const float4*)(&As[kk][ty*4]);
            float4 w = *(const float4*)(&Ws[kk][tx*4]);
            acc[0][0] += a.x*w.x; acc[0][1] += a.x*w.y; acc[0][2] += a.x*w.z; acc[0][3] += a.x*w.w;
            acc[1][0] += a.y*w.x; acc[1][1] += a.y*w.y; acc[1][2] += a.y*w.z; acc[1][3] += a.y*w.w;
            acc[2][0] += a.z*w.x; acc[2][1] += a.z*w.y; acc[2][2] += a.z*w.z; acc[2][3] += a.z*w.w;
            acc[3][0] += a.w*w.x; acc[3][1] += a.w*w.y; acc[3][2] += a.w*w.z; acc[3][3] += a.w*w.w;
        }
    }
    float4 bvv = *(const float4*)(bias + n0 + tx*4);
#pragma unroll
    for (int i = 0; i < 4; i++) {
        float4 o = make_float4(acc[i][0] + bvv.x, acc[i][1] + bvv.y,
                               acc[i][2] + bvv.z, acc[i][3] + bvv.w);
        int m = m0 + ty*4 + i;
        if (HEADMAJOR) {
            int b = m >> 10, l = m & 1023, h = n0 >> 6;
            *(float4*)(C + ((size_t)((b*16 + h)*1024 + l))*64 + tx*4) = o;
        } else {
            *(float4*)(C + (size_t)m * 1024 + n0 + tx*4) = o;
        }
    }
}

// ============================================================
// Chord / bass features: [1024,12]@[12,1024] + bias -> head-major
// ============================================================
__global__ __launch_bounds__(256) void chordfeat(
    const int* __restrict__ pc, const int* __restrict__ bon,
    const float* __restrict__ Wc, const float* __restrict__ bc,
    const float* __restrict__ Wb, const float* __restrict__ bb,
    float* __restrict__ cf, float* __restrict__ bf)
{
    int idx = blockIdx.x * 256 + threadIdx.x;   // 0 .. L*D-1
    int l = idx >> 10, n = idx & 1023;
    float sc = bc[n], sb = bb[n];
#pragma unroll
    for (int p = 0; p < 12; p++) {
        sc += (float)pc[l*12 + p] * Wc[p*1024 + n];
        sb += (float)bon[l*12 + p] * Wb[p*1024 + n];
    }
    int h = n >> 6, hd = n & 63;
    cf[((size_t)h*1024 + l)*64 + hd] = sc;
    bf[((size_t)h*1024 + l)*64 + hd] = sb;
}

// ============================================================
// Scores: S[bh][q][k] = (pq.k + hq.cf + vq.bf) / 24  -> raw into attn buffer
// 64x64 tile, K=3x64=192, both operands transposed-on-store into smem
// ============================================================
__global__ __launch_bounds__(256) void score_gemm(
    const float* __restrict__ pq, const float* __restrict__ hq, const float* __restrict__ vq,
    const float* __restrict__ kmat, const float* __restrict__ cf, const float* __restrict__ bf,
    float* __restrict__ attn)
{
    const int bh = blockIdx.z, h = bh & 15;
    const int q0 = blockIdx.y * 64, n0 = blockIdx.x * 64;
    const float* Qp[3] = { pq + (size_t)bh*NL*NHD, hq + (size_t)bh*NL*NHD, vq + (size_t)bh*NL*NHD };
    const float* Kp[3] = { kmat + (size_t)bh*NL*NHD, cf + (size_t)h*NL*NHD, bf + (size_t)h*NL*NHD };
    const int tid = threadIdx.x;
    const int tx = tid & 15, ty = tid >> 4;
    __shared__ __align__(16) float As[16][64];
    __shared__ __align__(16) float Bs[16][64];
    float acc[4][4] = {};
    const int lr = tid >> 2, lk = (tid & 3) * 4;

#pragma unroll
    for (int seg = 0; seg < 3; seg++) {
        const float* Q = Qp[seg];
        const float* K = Kp[seg];
#pragma unroll
        for (int d0 = 0; d0 < 64; d0 += 16) {
            float4 av = *(const float4*)(Q + (size_t)(q0 + lr)*64 + d0 + lk);
            float4 bv = *(const float4*)(K + (size_t)(n0 + lr)*64 + d0 + lk);
            __syncthreads();
            As[lk+0][lr] = av.x; As[lk+1][lr] = av.y;
            As[lk+2][lr] = av.z; As[lk+3][lr] = av.w;
            Bs[lk+0][lr] = bv.x; Bs[lk+1][lr] = bv.y;
            Bs[lk+2][lr] = bv.z; Bs[lk+3][lr] = bv.w;
            __syncthreads();
#pragma unroll
            for (int kk = 0; kk < 16; kk++) {
                float4 a = *(const float4*)(&As[kk][ty*4]);
                float4 w = *(const float4*)(&Bs[kk][tx*4]);
                acc[0][0] += a.x*w.x; acc[0][1] += a.x*w.y; acc[0][2] += a.x*w.z; acc[0][3] += a.x*w.w;
                acc[1][0] += a.y*w.x; acc[1][1] += a.y*w.y; acc[1][2] += a.y*w.z; acc[1][3] += a.y*w.w;
                acc[2][0] += a.z*w.x; acc[2][1] += a.z*w.y; acc[2][2] += a.z*w.z; acc[2][3] += a.z*w.w;
                acc[3][0] += a.w*w.x; acc[3][1] += a.w*w.y; acc[3][2] += a.w*w.z; acc[3][3] += a.w*w.w;
            }
        }
    }
    const float sc = 1.0f / 24.0f;   // (HD^-0.5)/3 = 0.125/3
#pragma unroll
    for (int i = 0; i < 4; i++) {
        float4 o = make_float4(acc[i][0]*sc, acc[i][1]*sc, acc[i][2]*sc, acc[i][3]*sc);
        *(float4*)(attn + ((size_t)bh*NL + q0 + ty*4 + i)*NL + n0 + tx*4) = o;
    }
}

// ============================================================
// Row softmax in place: one block per (bh,q) row of 1024
// ============================================================
__global__ __launch_bounds__(256) void softmax_rows(float* __restrict__ attn)
{
    const size_t row = blockIdx.x;
    float4* p = (float4*)(attn + row * 1024);
    const int tid = threadIdx.x;
    float4 x = p[tid];
    __shared__ float sm[8];
    __shared__ float ss[8];

    float m = fmaxf(fmaxf(x.x, x.y), fmaxf(x.z, x.w));
#pragma unroll
    for (int o = 16; o > 0; o >>= 1) m = fmaxf(m, __shfl_xor_sync(0xffffffffu, m, o));
    if ((tid & 31) == 0) sm[tid >> 5] = m;
    __syncthreads();
    m = sm[0];
#pragma unroll
    for (int i = 1; i < 8; i++) m = fmaxf(m, sm[i]);

    float e0 = __expf(x.x - m), e1 = __expf(x.y - m);
    float e2 = __expf(x.z - m), e3 = __expf(x.w - m);
    float s = e0 + e1 + e2 + e3;
#pragma unroll
    for (int o = 16; o > 0; o >>= 1) s += __shfl_xor_sync(0xffffffffu, s, o);
    if ((tid & 31) == 0) ss[tid >> 5] = s;
    __syncthreads();
    s = ss[0];
#pragma unroll
    for (int i = 1; i < 8; i++) s += ss[i];

    float inv = 1.0f / s;
    p[tid] = make_float4(e0*inv, e1*inv, e2*inv, e3*inv);
}

// ============================================================
// Context: ctx[b,q,h*64+hd] = sum_k attn[bh][q][k] * v[bh][k][hd]
// 64(q) x 64(hd) tile, K=1024
// ============================================================
__global__ __launch_bounds__(256) void ctx_gemm(
    const float* __restrict__ attn, const float* __restrict__ v, float* __restrict__ ctx)
{
    const int bh = blockIdx.y, q0 = blockIdx.x * 64;
    const float* A = attn + (size_t)bh * NL * NL;
    const float* V = v + (size_t)bh * NL * NHD;
    const int tid = threadIdx.x;
    const int tx = tid & 15, ty = tid >> 4;
    __shared__ __align__(16) float As[16][64];
    __shared__ __align__(16) float Ws[16][64];
    float acc[4][4] = {};
    const int lr = tid >> 2, lk = (tid & 3) * 4;
    const int wk = tid >> 4, wn = (tid & 15) * 4;

    for (int k0 = 0; k0 < 1024; k0 += 16) {
        float4 av = *(const float4*)(A + (size_t)(q0 + lr)*1024 + k0 + lk);
        float4 wv = *(const float4*)(V + (size_t)(k0 + wk)*64 + wn);
        __syncthreads();
        As[lk+0][lr] = av.x; As[lk+1][lr] = av.y;
        As[lk+2][lr] = av.z; As[lk+3][lr] = av.w;
        *(float4*)(&Ws[wk][wn]) = wv;
        __syncthreads();
#pragma unroll
        for (int kk = 0; kk < 16; kk++) {
            float4 a = *(const float4*)(&As[kk][ty*4]);
            float4 w = *(const float4*)(&Ws[kk][tx*4]);
            acc[0][0] += a.x*w.x; acc[0][1] += a.x*w.y; acc[0][2] += a.x*w.z; acc[0][3] += a.x*w.w;
            acc[1][0] += a.y*w.x; acc[1][1] += a.y*w.y; acc[1][2] += a.y*w.z; acc[1][3] += a.y*w.w;
            acc[2][0] += a.z*w.x; acc[2][1] += a.z*w.y; acc[2][2] += a.z*w.z; acc[2][3] += a.z*w.w;
            acc[3][0] += a.w*w.x; acc[3][1] += a.w*w.y; acc[3][2] += a.w*w.z; acc[3][3] += a.w*w.w;
        }
    }
    const int b = bh >> 4, h = bh & 15;
#pragma unroll
    for (int i = 0; i < 4; i++) {
        float4 o = make_float4(acc[i][0], acc[i][1], acc[i][2], acc[i][3]);
        int l = q0 + ty*4 + i;
        *(float4*)(ctx + ((size_t)(b*1024 + l))*1024 + h*64 + tx*4) = o;
    }
}

// ============================================================
// Launch
// ============================================================
extern "C" void kernel_launch(void* const* d_in, const int* in_sizes, int n_in,
                              void* d_out, int out_size)
{
    const float* query = (const float*)d_in[0];
    const float* key   = (const float*)d_in[1];
    const float* value = (const float*)d_in[2];
    const int*   pc    = (const int*)d_in[3];
    const int*   bon   = (const int*)d_in[4];
    const float* Wpq = (const float*)d_in[5],  *bpq = (const float*)d_in[6];
    const float* Whq = (const float*)d_in[7],  *bhq = (const float*)d_in[8];
    const float* Wvq = (const float*)d_in[9],  *bvq = (const float*)d_in[10];
    const float* Wk  = (const float*)d_in[11], *bk  = (const float*)d_in[12];
    const float* Wv  = (const float*)d_in[13], *bv  = (const float*)d_in[14];
    const float* Wc  = (const float*)d_in[15], *bc  = (const float*)d_in[16];
    const float* Wb  = (const float*)d_in[17], *bb  = (const float*)d_in[18];
    const float* Wo  = (const float*)d_in[19], *bo  = (const float*)d_in[20];

    float *pq_p, *hq_p, *vq_p, *k_p, *v_p, *cf_p, *bf_p, *ctx_p;
    cudaGetSymbolAddress((void**)&pq_p,  g_pq);
    cudaGetSymbolAddress((void**)&hq_p,  g_hq);
    cudaGetSymbolAddress((void**)&vq_p,  g_vq);
    cudaGetSymbolAddress((void**)&k_p,   g_k);
    cudaGetSymbolAddress((void**)&v_p,   g_v);
    cudaGetSymbolAddress((void**)&cf_p,  g_cf);
    cudaGetSymbolAddress((void**)&bf_p,  g_bf);
    cudaGetSymbolAddress((void**)&ctx_p, g_ctx);

    float* out  = (float*)d_out;                       // (B,L,D)
    float* attn = out + (size_t)NB * NL * ND;          // (B,H,L,L)

    dim3 gg(16, 64), tt(256);
    sgemm_bias<true><<<gg, tt>>>(query, Wpq, bpq, pq_p);
    sgemm_bias<true><<<gg, tt>>>(query, Whq, bhq, hq_p);
    sgemm_bias<true><<<gg, tt>>>(query, Wvq, bvq, vq_p);
    sgemm_bias<true><<<gg, tt>>>(key,   Wk,  bk,  k_p);
    sgemm_bias<true><<<gg, tt>>>(value, Wv,  bv,  v_p);
    chordfeat<<<4096, 256>>>(pc, bon, Wc, bc, Wb, bb, cf_p, bf_p);
    score_gemm<<<dim3(16, 16, 64), 256>>>(pq_p, hq_p, vq_p, k_p, cf_p, bf_p, attn);
    softmax_rows<<<NBH * NL, 256>>>(attn);
    ctx_gemm<<<dim3(16, 64), 256>>>(attn, v_p, ctx_p);
    sgemm_bias<false><<<gg, tt>>>(ctx_p, Wo, bo, out);
}

// round 3
// speedup vs baseline: 2.8768x; 2.8768x over previous
#include <cuda_runtime.h>
#include <math.h>
#include <cstdint>

#define NB 4
#define NL 1024
#define ND 1024
#define NH 16
#define NHD 64
#define NBH (NB*NH)

// ---------------- scratch (device globals) ----------------
__device__ __align__(16) float g_pq[NBH*NL*NHD];
__device__ __align__(16) float g_hq[NBH*NL*NHD];
__device__ __align__(16) float g_vq[NBH*NL*NHD];
__device__ __align__(16) float g_k [NBH*NL*NHD];
__device__ __align__(16) float g_v [NBH*NL*NHD];
__device__ __align__(16) float g_vt[NBH*NL*NHD];
__device__ __align__(16) float g_cf[NH*NL*NHD];
__device__ __align__(16) float g_bf[NH*NL*NHD];
__device__ __align__(16) float g_ctx[NB*NL*ND];
__device__ __align__(16) float g_wt[6u*1024u*1024u];   // transposed (+tf32-rounded) weights
__device__ __align__(16) float g_qr[NB*NL*ND];         // tf32-rounded inputs
__device__ __align__(16) float g_kr[NB*NL*ND];
__device__ __align__(16) float g_vr[NB*NL*ND];

// ---------------- helpers ----------------
__device__ __forceinline__ float rnd_tf32(float x) {
    uint32_t u;
    asm("cvt.rna.tf32.f32 %0, %1;" : "=r"(u) : "f"(x));
    return __uint_as_float(u);
}
__device__ __forceinline__ void cpa16(uint32_t s, const void* g) {
    asm volatile("cp.async.cg.shared.global [%0], [%1], 16;" :: "r"(s), "l"(g) : "memory");
}
__device__ __forceinline__ uint32_t s2u(const void* p) {
    return (uint32_t)__cvta_generic_to_shared(p);
}

#define PITCH 36   // floats; bank = (4r + c) % 32 -> conflict-free fragment loads

// warp-level tf32 mma over one BKx(...) stage slice
template<int MSUB, int NSUB>
__device__ __forceinline__ void warp_mma(
    const float* __restrict__ As, const float* __restrict__ Bs,
    int mrow0, int ncol0, float (&acc)[MSUB][NSUB][4], int g, int t)
{
#pragma unroll
    for (int k8 = 0; k8 < 4; k8++) {
        uint32_t a[MSUB][4];
#pragma unroll
        for (int mi = 0; mi < MSUB; mi++) {
            const float* ap = As + (mrow0 + mi*16 + g)*PITCH + k8*8 + t;
            a[mi][0] = __float_as_uint(ap[0]);
            a[mi][1] = __float_as_uint(ap[8*PITCH]);
            a[mi][2] = __float_as_uint(ap[4]);
            a[mi][3] = __float_as_uint(ap[8*PITCH + 4]);
        }
        uint32_t b[NSUB][2];
#pragma unroll
        for (int ni = 0; ni < NSUB; ni++) {
            const float* bp = Bs + (ncol0 + ni*8 + g)*PITCH + k8*8 + t;
            b[ni][0] = __float_as_uint(bp[0]);
            b[ni][1] = __float_as_uint(bp[4]);
        }
#pragma unroll
        for (int mi = 0; mi < MSUB; mi++)
#pragma unroll
            for (int ni = 0; ni < NSUB; ni++) {
                asm volatile(
                    "mma.sync.aligned.m16n8k8.row.col.f32.tf32.tf32.f32 "
                    "{%0,%1,%2,%3}, {%4,%5,%6,%7}, {%8,%9}, {%0,%1,%2,%3};"
                    : "+f"(acc[mi][ni][0]), "+f"(acc[mi][ni][1]),
                      "+f"(acc[mi][ni][2]), "+f"(acc[mi][ni][3])
                    : "r"(a[mi][0]), "r"(a[mi][1]), "r"(a[mi][2]), "r"(a[mi][3]),
                      "r"(b[ni][0]), "r"(b[ni][1]));
            }
    }
}

// ============================================================
// mma_gemm: C[4096x1024] = A[4096x1024] @ BT^T + bias, BT=[N,K]
// 128x128 block, BK=32, 8 warps (2m x 4n), warp 64x32
// ============================================================
template<bool HEADMAJOR, bool ROUND>
__global__ void __launch_bounds__(256, 2) mma_gemm(
    const float* __restrict__ A, const float* __restrict__ BT,
    const float* __restrict__ bias, float* __restrict__ C)
{
    extern __shared__ float sm[];
    float* Asb[2] = { sm, sm + 128*PITCH };
    float* Bsb[2] = { sm + 2*128*PITCH, sm + 3*128*PITCH };
    const int tid = threadIdx.x, lane = tid & 31, wid = tid >> 5;
    const int wm = wid & 1, wn = wid >> 1;
    const int g = lane >> 2, t = lane & 3;
    const int m0 = blockIdx.y * 128, n0 = blockIdx.x * 128;

    float acc[4][4][4] = {};

#define LOAD_STAGE(i, s) do {                                              \
        int k0 = (i) * 32;                                                 \
        _Pragma("unroll")                                                  \
        for (int it = 0; it < 4; it++) {                                   \
            int j = it*256 + tid;                                          \
            int r = j >> 3, c = j & 7;                                     \
            cpa16(s2u(Asb[s] + r*PITCH + c*4), A  + (size_t)(m0+r)*1024 + k0 + c*4); \
            cpa16(s2u(Bsb[s] + r*PITCH + c*4), BT + (size_t)(n0+r)*1024 + k0 + c*4); \
        }                                                                  \
        asm volatile("cp.async.commit_group;" ::: "memory");               \
    } while (0)

    LOAD_STAGE(0, 0);
    for (int i = 0; i < 32; i++) {
        int s = i & 1;
        if (i + 1 < 32) {
            LOAD_STAGE(i + 1, s ^ 1);
            asm volatile("cp.async.wait_group 1;" ::: "memory");
        } else {
            asm volatile("cp.async.wait_group 0;" ::: "memory");
        }
        __syncthreads();
        warp_mma<4,4>(Asb[s], Bsb[s], wm*64, wn*32, acc, g, t);
        __syncthreads();
    }
#undef LOAD_STAGE

#pragma unroll
    for (int mi = 0; mi < 4; mi++)
#pragma unroll
        for (int ni = 0; ni < 4; ni++) {
            int mrow = m0 + wm*64 + mi*16 + g;
            int ncol = n0 + wn*32 + ni*8 + t*2;
            float b0 = bias[ncol], b1 = bias[ncol+1];
            float v00 = acc[mi][ni][0] + b0, v01 = acc[mi][ni][1] + b1;
            float v10 = acc[mi][ni][2] + b0, v11 = acc[mi][ni][3] + b1;
            if (ROUND) { v00 = rnd_tf32(v00); v01 = rnd_tf32(v01);
                         v10 = rnd_tf32(v10); v11 = rnd_tf32(v11); }
            if (HEADMAJOR) {
                int h = ncol >> 6, hd = ncol & 63;
                int b = mrow >> 10, l = mrow & 1023;
                float* d0 = g_pq; // placeholder unused
                (void)d0;
                size_t base0 = ((size_t)((b*16 + h)*1024 + l))*64 + hd;
                size_t base1 = ((size_t)((b*16 + h)*1024 + (l+8 <= 1023 ? l : l)))*64; (void)base1;
                *(float2*)(C + base0) = make_float2(v00, v01);
                int l2 = (mrow + 8) & 1023, b2 = (mrow + 8) >> 10;
                *(float2*)(C + ((size_t)((b2*16 + h)*1024 + l2))*64 + hd) = make_float2(v10, v11);
            } else {
                *(float2*)(C + (size_t)mrow*1024 + ncol) = make_float2(v00, v01);
                *(float2*)(C + (size_t)(mrow+8)*1024 + ncol) = make_float2(v10, v11);
            }
        }
}

// ============================================================
// mma_score: S[bh,q,n] = (pq.k + hq.cf + vq.bf)/24, 128x128, K=3x64
// ============================================================
__global__ void __launch_bounds__(256, 2) mma_score(
    const float* __restrict__ pq, const float* __restrict__ hq, const float* __restrict__ vq,
    const float* __restrict__ kf, const float* __restrict__ cf, const float* __restrict__ bff,
    float* __restrict__ attn)
{
    extern __shared__ float sm[];
    float* Asb[2] = { sm, sm + 128*PITCH };
    float* Bsb[2] = { sm + 2*128*PITCH, sm + 3*128*PITCH };
    const int tid = threadIdx.x, lane = tid & 31, wid = tid >> 5;
    const int wm = wid & 1, wn = wid >> 1;
    const int g = lane >> 2, t = lane & 3;
    const int bh = blockIdx.z, h = bh & 15;
    const int q0 = blockIdx.y * 128, n0 = blockIdx.x * 128;

    const size_t ob = (size_t)bh * NL * 64;
    const size_t oh = (size_t)h  * NL * 64;
    const float* Aseg[3] = { pq + ob + (size_t)q0*64, hq + ob + (size_t)q0*64, vq + ob + (size_t)q0*64 };
    const float* Bseg[3] = { kf + ob + (size_t)n0*64, cf + oh + (size_t)n0*64, bff + oh + (size_t)n0*64 };

    float acc[4][4][4] = {};

#define LOAD_STAGE_S(i, s) do {                                            \
        int seg = (i) >> 1, ko = ((i) & 1) * 32;                           \
        const float* Ab = Aseg[seg]; const float* Bb = Bseg[seg];          \
        _Pragma("unroll")                                                  \
        for (int it = 0; it < 4; it++) {                                   \
            int j = it*256 + tid;                                          \
            int r = j >> 3, c = j & 7;                                     \
            cpa16(s2u(Asb[s] + r*PITCH + c*4), Ab + (size_t)r*64 + ko + c*4); \
            cpa16(s2u(Bsb[s] + r*PITCH + c*4), Bb + (size_t)r*64 + ko + c*4); \
        }                                                                  \
        asm volatile("cp.async.commit_group;" ::: "memory");               \
    } while (0)

    LOAD_STAGE_S(0, 0);
    for (int i = 0; i < 6; i++) {
        int s = i & 1;
        if (i + 1 < 6) {
            LOAD_STAGE_S(i + 1, s ^ 1);
            asm volatile("cp.async.wait_group 1;" ::: "memory");
        } else {
            asm volatile("cp.async.wait_group 0;" ::: "memory");
        }
        __syncthreads();
        warp_mma<4,4>(Asb[s], Bsb[s], wm*64, wn*32, acc, g, t);
        __syncthreads();
    }
#undef LOAD_STAGE_S

    const float sc = 1.0f / 24.0f;
#pragma unroll
    for (int mi = 0; mi < 4; mi++)
#pragma unroll
        for (int ni = 0; ni < 4; ni++) {
            int mrow = q0 + wm*64 + mi*16 + g;
            int ncol = n0 + wn*32 + ni*8 + t*2;
            float* d0 = attn + ((size_t)bh*NL + mrow)*NL + ncol;
            float* d1 = attn + ((size_t)bh*NL + mrow + 8)*NL + ncol;
            *(float2*)d0 = make_float2(acc[mi][ni][0]*sc, acc[mi][ni][1]*sc);
            *(float2*)d1 = make_float2(acc[mi][ni][2]*sc, acc[mi][ni][3]*sc);
        }
}

// ============================================================
// mma_ctx: ctx[b,q,h*64+n] = sum_k attn[bh,q,k] * vt[bh,n,k]; 128x64, K=1024
// 8 warps (2m x 4n), warp 64x16 -> msub=4, nsub=2
// ============================================================
__global__ void __launch_bounds__(256, 2) mma_ctx(
    const float* __restrict__ attn, const float* __restrict__ vt, float* __restrict__ ctx)
{
    extern __shared__ float sm[];
    float* Asb[2] = { sm, sm + 128*PITCH };
    float* Bsb[2] = { sm + 2*128*PITCH, sm + 2*128*PITCH + 64*PITCH };
    const int tid = threadIdx.x, lane = tid & 31, wid = tid >> 5;
    const int wm = wid & 1, wn = wid >> 1;
    const int g = lane >> 2, t = lane & 3;
    const int bh = blockIdx.y, q0 = blockIdx.x * 128;
    const float* Ab = attn + (size_t)bh*NL*NL + (size_t)q0*NL;
    const float* Bb = vt   + (size_t)bh*64*NL;

    float acc[4][2][4] = {};

#define LOAD_STAGE_C(i, s) do {                                            \
        int k0 = (i) * 32;                                                 \
        _Pragma("unroll")                                                  \
        for (int it = 0; it < 4; it++) {                                   \
            int j = it*256 + tid;                                          \
            int r = j >> 3, c = j & 7;                                     \
            cpa16(s2u(Asb[s] + r*PITCH + c*4), Ab + (size_t)r*NL + k0 + c*4); \
        }                                                                  \
        _Pragma("unroll")                                                  \
        for (int it = 0; it < 2; it++) {                                   \
            int j = it*256 + tid;                                          \
            int r = j >> 3, c = j & 7;                                     \
            cpa16(s2u(Bsb[s] + r*PITCH + c*4), Bb + (size_t)r*NL + k0 + c*4); \
        }                                                                  \
        asm volatile("cp.async.commit_group;" ::: "memory");               \
    } while (0)

    LOAD_STAGE_C(0, 0);
    for (int i = 0; i < 32; i++) {
        int s = i & 1;
        if (i + 1 < 32) {
            LOAD_STAGE_C(i + 1, s ^ 1);
            asm volatile("cp.async.wait_group 1;" ::: "memory");
        } else {
            asm volatile("cp.async.wait_group 0;" ::: "memory");
        }
        __syncthreads();
        warp_mma<4,2>(Asb[s], Bsb[s], wm*64, wn*16, acc, g, t);
        __syncthreads();
    }
#undef LOAD_STAGE_C

    const int b = bh >> 4, hh = bh & 15;
#pragma unroll
    for (int mi = 0; mi < 4; mi++)
#pragma unroll
        for (int ni = 0; ni < 2; ni++) {
            int mrow = q0 + wm*64 + mi*16 + g;
            int ncol = wn*16 + ni*8 + t*2;
            float v00 = rnd_tf32(acc[mi][ni][0]), v01 = rnd_tf32(acc[mi][ni][1]);
            float v10 = rnd_tf32(acc[mi][ni][2]), v11 = rnd_tf32(acc[mi][ni][3]);
            *(float2*)(ctx + ((size_t)(b*1024 + mrow))*1024 + hh*64 + ncol) = make_float2(v00, v01);
            *(float2*)(ctx + ((size_t)(b*1024 + mrow + 8))*1024 + hh*64 + ncol) = make_float2(v10, v11);
        }
}

// ============================================================
// transpose (+ tf32 round): dst[C,R] = src[R,C]^T, batch over z
// ============================================================
__global__ void __launch_bounds__(256) transpose_f32(
    const float* __restrict__ src, float* __restrict__ dst, int R, int C)
{
    __shared__ float tbuf[32][33];
    const int bx = blockIdx.x * 32, by = blockIdx.y * 32;
    const size_t base = (size_t)blockIdx.z * R * C;
    const int x = threadIdx.x, y0 = threadIdx.y;
#pragma unroll
    for (int dy = 0; dy < 32; dy += 8)
        tbuf[y0+dy][x] = src[base + (size_t)(by + y0 + dy)*C + bx + x];
    __syncthreads();
#pragma unroll
    for (int dy = 0; dy < 32; dy += 8)
        dst[base + (size_t)(bx + y0 + dy)*R + by + x] = rnd_tf32(tbuf[x][y0+dy]);
}

// ============================================================
// tf32-round copy
// ============================================================
__global__ void __launch_bounds__(256) round_copy(
    const float4* __restrict__ in, float4* __restrict__ out)
{
    int i = blockIdx.x * 256 + threadIdx.x;
    float4 v = in[i];
    v.x = rnd_tf32(v.x); v.y = rnd_tf32(v.y);
    v.z = rnd_tf32(v.z); v.w = rnd_tf32(v.w);
    out[i] = v;
}

// ============================================================
// chord/bass features -> head-major (+ round)
// ============================================================
__global__ __launch_bounds__(256) void chordfeat(
    const int* __restrict__ pc, const int* __restrict__ bon,
    const float* __restrict__ Wc, const float* __restrict__ bc,
    const float* __restrict__ Wb, const float* __restrict__ bb,
    float* __restrict__ cf, float* __restrict__ bf)
{
    int idx = blockIdx.x * 256 + threadIdx.x;
    int l = idx >> 10, n = idx & 1023;
    float sc = bc[n], sb = bb[n];
#pragma unroll
    for (int p = 0; p < 12; p++) {
        sc += (float)pc[l*12 + p] * Wc[p*1024 + n];
        sb += (float)bon[l*12 + p] * Wb[p*1024 + n];
    }
    int h = n >> 6, hd = n & 63;
    cf[((size_t)h*1024 + l)*64 + hd] = rnd_tf32(sc);
    bf[((size_t)h*1024 + l)*64 + hd] = rnd_tf32(sb);
}

// ============================================================
// row softmax in place (+ round output for tf32 mma consumption)
// ============================================================
__global__ __launch_bounds__(256) void softmax_rows(float* __restrict__ attn)
{
    const size_t row = blockIdx.x;
    float4* p = (float4*)(attn + row * 1024);
    const int tid = threadIdx.x;
    float4 x = p[tid];
    __shared__ float smx[8];
    __shared__ float ssm[8];

    float m = fmaxf(fmaxf(x.x, x.y), fmaxf(x.z, x.w));
#pragma unroll
    for (int o = 16; o > 0; o >>= 1) m = fmaxf(m, __shfl_xor_sync(0xffffffffu, m, o));
    if ((tid & 31) == 0) smx[tid >> 5] = m;
    __syncthreads();
    m = smx[0];
#pragma unroll
    for (int i = 1; i < 8; i++) m = fmaxf(m, smx[i]);

    float e0 = __expf(x.x - m), e1 = __expf(x.y - m);
    float e2 = __expf(x.z - m), e3 = __expf(x.w - m);
    float s = e0 + e1 + e2 + e3;
#pragma unroll
    for (int o = 16; o > 0; o >>= 1) s += __shfl_xor_sync(0xffffffffu, s, o);
    if ((tid & 31) == 0) ssm[tid >> 5] = s;
    __syncthreads();
    s = ssm[0];
#pragma unroll
    for (int i = 1; i < 8; i++) s += ssm[i];

    float inv = 1.0f / s;
    p[tid] = make_float4(rnd_tf32(e0*inv), rnd_tf32(e1*inv),
                         rnd_tf32(e2*inv), rnd_tf32(e3*inv));
}

// ============================================================
// launch
// ============================================================
extern "C" void kernel_launch(void* const* d_in, const int* in_sizes, int n_in,
                              void* d_out, int out_size)
{
    const float* query = (const float*)d_in[0];
    const float* key   = (const float*)d_in[1];
    const float* value = (const float*)d_in[2];
    const int*   pc    = (const int*)d_in[3];
    const int*   bon   = (const int*)d_in[4];
    const float* Wpq = (const float*)d_in[5],  *bpq = (const float*)d_in[6];
    const float* Whq = (const float*)d_in[7],  *bhq = (const float*)d_in[8];
    const float* Wvq = (const float*)d_in[9],  *bvq = (const float*)d_in[10];
    const float* Wk  = (const float*)d_in[11], *bk  = (const float*)d_in[12];
    const float* Wv  = (const float*)d_in[13], *bv  = (const float*)d_in[14];
    const float* Wc  = (const float*)d_in[15], *bc  = (const float*)d_in[16];
    const float* Wb  = (const float*)d_in[17], *bb  = (const float*)d_in[18];
    const float* Wo  = (const float*)d_in[19], *bo  = (const float*)d_in[20];

    float *pq_p, *hq_p, *vq_p, *k_p, *v_p, *vt_p, *cf_p, *bf_p, *ctx_p, *wt_p;
    float *qr_p, *kr_p, *vr_p;
    cudaGetSymbolAddress((void**)&pq_p,  g_pq);
    cudaGetSymbolAddress((void**)&hq_p,  g_hq);
    cudaGetSymbolAddress((void**)&vq_p,  g_vq);
    cudaGetSymbolAddress((void**)&k_p,   g_k);
    cudaGetSymbolAddress((void**)&v_p,   g_v);
    cudaGetSymbolAddress((void**)&vt_p,  g_vt);
    cudaGetSymbolAddress((void**)&cf_p,  g_cf);
    cudaGetSymbolAddress((void**)&bf_p,  g_bf);
    cudaGetSymbolAddress((void**)&ctx_p, g_ctx);
    cudaGetSymbolAddress((void**)&wt_p,  g_wt);
    cudaGetSymbolAddress((void**)&qr_p,  g_qr);
    cudaGetSymbolAddress((void**)&kr_p,  g_kr);
    cudaGetSymbolAddress((void**)&vr_p,  g_vr);

    float* WpqT = wt_p + 0u*1024u*1024u;
    float* WhqT = wt_p + 1u*1024u*1024u;
    float* WvqT = wt_p + 2u*1024u*1024u;
    float* WkT  = wt_p + 3u*1024u*1024u;
    float* WvT  = wt_p + 4u*1024u*1024u;
    float* WoT  = wt_p + 5u*1024u*1024u;

    float* out  = (float*)d_out;
    float* attn = out + (size_t)NB * NL * ND;

    const int SM_BIG = 4 * 128 * PITCH * 4;                 // 73728
    const int SM_CTX = (2*128*PITCH + 2*64*PITCH) * 4;      // 55296
    cudaFuncSetAttribute(mma_gemm<true,true>,   cudaFuncAttributeMaxDynamicSharedMemorySize, SM_BIG);
    cudaFuncSetAttribute(mma_gemm<false,false>, cudaFuncAttributeMaxDynamicSharedMemorySize, SM_BIG);
    cudaFuncSetAttribute(mma_score,             cudaFuncAttributeMaxDynamicSharedMemorySize, SM_BIG);
    cudaFuncSetAttribute(mma_ctx,               cudaFuncAttributeMaxDynamicSharedMemorySize, SM_CTX);

    // tf32-round inputs + weights
    round_copy<<<4096, 256>>>((const float4*)query, (float4*)qr_p);
    round_copy<<<4096, 256>>>((const float4*)key,   (float4*)kr_p);
    round_copy<<<4096, 256>>>((const float4*)value, (float4*)vr_p);

    dim3 tb(32, 8);
    transpose_f32<<<dim3(32, 32, 1), tb>>>(Wpq, WpqT, 1024, 1024);
    transpose_f32<<<dim3(32, 32, 1), tb>>>(Whq, WhqT, 1024, 1024);
    transpose_f32<<<dim3(32, 32, 1), tb>>>(Wvq, WvqT, 1024, 1024);
    transpose_f32<<<dim3(32, 32, 1), tb>>>(Wk,  WkT,  1024, 1024);
    transpose_f32<<<dim3(32, 32, 1), tb>>>(Wv,  WvT,  1024, 1024);
    transpose_f32<<<dim3(32, 32, 1), tb>>>(Wo,  WoT,  1024, 1024);

    dim3 gg(8, 32);
    mma_gemm<true,true><<<gg, 256, SM_BIG>>>(qr_p, WpqT, bpq, pq_p);
    mma_gemm<true,true><<<gg, 256, SM_BIG>>>(qr_p, WhqT, bhq, hq_p);
    mma_gemm<true,true><<<gg, 256, SM_BIG>>>(qr_p, WvqT, bvq, vq_p);
    mma_gemm<true,true><<<gg, 256, SM_BIG>>>(kr_p, WkT,  bk,  k_p);
    mma_gemm<true,true><<<gg, 256, SM_BIG>>>(vr_p, WvT,  bv,  v_p);

    transpose_f32<<<dim3(2, 32, NBH), tb>>>(v_p, vt_p, 1024, 64);   // vt[bh][hd][l]
    chordfeat<<<4096, 256>>>(pc, bon, Wc, bc, Wb, bb, cf_p, bf_p);

    mma_score<<<dim3(8, 8, NBH), 256, SM_BIG>>>(pq_p, hq_p, vq_p, k_p, cf_p, bf_p, attn);
    softmax_rows<<<NBH * NL, 256>>>(attn);
    mma_ctx<<<dim3(8, NBH), 256, SM_CTX>>>(attn, vt_p, ctx_p);
    mma_gemm<false,false><<<gg, 256, SM_BIG>>>(ctx_p, WoT, bo, out);
}

// round 4
// speedup vs baseline: 3.4236x; 1.1901x over previous
#include <cuda_runtime.h>
#include <math.h>
#include <cstdint>

#define NB 4
#define NL 1024
#define ND 1024
#define NH 16
#define NHD 64
#define NBH (NB*NH)

// ---------------- scratch (device globals) ----------------
__device__ __align__(16) float g_qcat[NBH*NL*192];     // [bh][l][pq|hq|vq]
__device__ __align__(16) float g_kcat[NBH*NL*192];     // [bh][l][k|cf|bf]
__device__ __align__(16) float g_v [NBH*NL*NHD];
__device__ __align__(16) float g_vt[NBH*NL*NHD];
__device__ __align__(16) float g_ctx[NB*NL*ND];
__device__ __align__(16) float g_wt[6u*1024u*1024u];   // transposed (+tf32-rounded) weights
__device__ __align__(16) float g_qr[NB*NL*ND];         // tf32-rounded inputs
__device__ __align__(16) float g_kr[NB*NL*ND];
__device__ __align__(16) float g_vr[NB*NL*ND];
__device__ __align__(16) float g_bcat[3072];

// ---------------- helpers ----------------
__device__ __forceinline__ float rnd_tf32(float x) {
    uint32_t u;
    asm("cvt.rna.tf32.f32 %0, %1;" : "=r"(u) : "f"(x));
    return __uint_as_float(u);
}
__device__ __forceinline__ void cpa16(uint32_t s, const void* g) {
    asm volatile("cp.async.cg.shared.global [%0], [%1], 16;" :: "r"(s), "l"(g) : "memory");
}
__device__ __forceinline__ uint32_t s2u(const void* p) {
    return (uint32_t)__cvta_generic_to_shared(p);
}
__device__ __forceinline__ void ldsm4(uint32_t (&r)[4], uint32_t a) {
    asm volatile("ldmatrix.sync.aligned.m8n8.x4.shared.b16 {%0,%1,%2,%3}, [%4];"
        : "=r"(r[0]), "=r"(r[1]), "=r"(r[2]), "=r"(r[3]) : "r"(a));
}
__device__ __forceinline__ void ldsm2(uint32_t (&r)[2], uint32_t a) {
    asm volatile("ldmatrix.sync.aligned.m8n8.x2.shared.b16 {%0,%1}, [%2];"
        : "=r"(r[0]), "=r"(r[1]) : "r"(a));
}

#define PITCH 36   // floats; rows stride 144B -> 16B aligned, ldmatrix conflict-free

// warp-level tf32 mma over one BK=32 stage; fragments via ldmatrix
template<int MSUB, int NSUB>
__device__ __forceinline__ void warp_mma(
    const float* __restrict__ As, const float* __restrict__ Bs,
    int mrow0, int ncol0, float (&acc)[MSUB][NSUB][4],
    int rA, int cA, int rB, int cB)
{
#pragma unroll
    for (int k8 = 0; k8 < 4; k8++) {
        uint32_t a[MSUB][4];
#pragma unroll
        for (int mi = 0; mi < MSUB; mi++)
            ldsm4(a[mi], s2u(As + (mrow0 + mi*16 + rA)*PITCH + k8*8 + cA));
        uint32_t b[NSUB][2];
#pragma unroll
        for (int ni = 0; ni < NSUB; ni++)
            ldsm2(b[ni], s2u(Bs + (ncol0 + ni*8 + rB)*PITCH + k8*8 + cB));
#pragma unroll
        for (int mi = 0; mi < MSUB; mi++)
#pragma unroll
            for (int ni = 0; ni < NSUB; ni++) {
                asm volatile(
                    "mma.sync.aligned.m16n8k8.row.col.f32.tf32.tf32.f32 "
                    "{%0,%1,%2,%3}, {%4,%5,%6,%7}, {%8,%9}, {%0,%1,%2,%3};"
                    : "+f"(acc[mi][ni][0]), "+f"(acc[mi][ni][1]),
                      "+f"(acc[mi][ni][2]), "+f"(acc[mi][ni][3])
                    : "r"(a[mi][0]), "r"(a[mi][1]), "r"(a[mi][2]), "r"(a[mi][3]),
                      "r"(b[ni][0]), "r"(b[ni][1]));
            }
    }
}

// output layouts
#define LAY_FLAT 0   // C[m][1024]
#define LAY_HEAD 1   // C[bh][l][64]          (N=1024)
#define LAY_QCAT 2   // Qcat[bh][l][192], seg = n>>10  (N=3072)
#define LAY_KCAT 3   // Kcat[bh][l][192], seg 0        (N=1024)

template<int LAYOUT>
__device__ __forceinline__ float* out_addr(float* C, int mrow, int ncol) {
    if (LAYOUT == LAY_FLAT) return C + (size_t)mrow*1024 + ncol;
    int b = mrow >> 10, l = mrow & 1023;
    if (LAYOUT == LAY_HEAD) {
        int h = ncol >> 6, hd = ncol & 63;
        return C + ((size_t)((b*16 + h)*1024 + l))*64 + hd;
    }
    if (LAYOUT == LAY_QCAT) {
        int seg = ncol >> 10, nn = ncol & 1023;
        int h = nn >> 6, hd = nn & 63;
        return C + ((size_t)((b*16 + h)*1024 + l))*192 + seg*64 + hd;
    }
    // LAY_KCAT
    int h = ncol >> 6, hd = ncol & 63;
    return C + ((size_t)((b*16 + h)*1024 + l))*192 + hd;
}

// ============================================================
// mma_gemm: C = A[4096x1024] @ BT^T + bias, BT=[N,K]
// 128x128 block, BK=32, 8 warps (2m x 4n)
// ============================================================
template<int LAYOUT, bool ROUND>
__global__ void __launch_bounds__(256, 2) mma_gemm(
    const float* __restrict__ A, const float* __restrict__ BT,
    const float* __restrict__ bias, float* __restrict__ C)
{
    extern __shared__ float sm[];
    float* Asb[2] = { sm, sm + 128*PITCH };
    float* Bsb[2] = { sm + 2*128*PITCH, sm + 3*128*PITCH };
    const int tid = threadIdx.x, lane = tid & 31, wid = tid >> 5;
    const int wm = wid & 1, wn = wid >> 1;
    const int g = lane >> 2, t = lane & 3;
    const int rA = ((lane >> 3) & 1)*8 + (lane & 7), cA = (lane >> 4)*4;
    const int rB = lane & 7, cB = ((lane >> 3) & 1)*4;
    const int m0 = blockIdx.y * 128, n0 = blockIdx.x * 128;

    float acc[4][4][4] = {};

#define LOAD_STAGE(i, s) do {                                              \
        int k0 = (i) * 32;                                                 \
        _Pragma("unroll")                                                  \
        for (int it = 0; it < 4; it++) {                                   \
            int j = it*256 + tid;                                          \
            int r = j >> 3, c = j & 7;                                     \
            cpa16(s2u(Asb[s] + r*PITCH + c*4), A  + (size_t)(m0+r)*1024 + k0 + c*4); \
            cpa16(s2u(Bsb[s] + r*PITCH + c*4), BT + (size_t)(n0+r)*1024 + k0 + c*4); \
        }                                                                  \
        asm volatile("cp.async.commit_group;" ::: "memory");               \
    } while (0)

    LOAD_STAGE(0, 0);
    for (int i = 0; i < 32; i++) {
        int s = i & 1;
        if (i + 1 < 32) {
            LOAD_STAGE(i + 1, s ^ 1);
            asm volatile("cp.async.wait_group 1;" ::: "memory");
        } else {
            asm volatile("cp.async.wait_group 0;" ::: "memory");
        }
        __syncthreads();
        warp_mma<4,4>(Asb[s], Bsb[s], wm*64, wn*32, acc, rA, cA, rB, cB);
        __syncthreads();
    }
#undef LOAD_STAGE

#pragma unroll
    for (int mi = 0; mi < 4; mi++)
#pragma unroll
        for (int ni = 0; ni < 4; ni++) {
            int mrow = m0 + wm*64 + mi*16 + g;
            int ncol = n0 + wn*32 + ni*8 + t*2;
            float b0 = bias[ncol], b1 = bias[ncol+1];
            float v00 = acc[mi][ni][0] + b0, v01 = acc[mi][ni][1] + b1;
            float v10 = acc[mi][ni][2] + b0, v11 = acc[mi][ni][3] + b1;
            if (ROUND) { v00 = rnd_tf32(v00); v01 = rnd_tf32(v01);
                         v10 = rnd_tf32(v10); v11 = rnd_tf32(v11); }
            *(float2*)out_addr<LAYOUT>(C, mrow,     ncol) = make_float2(v00, v01);
            *(float2*)out_addr<LAYOUT>(C, mrow + 8, ncol) = make_float2(v10, v11);
        }
}

// ============================================================
// mma_score: S[bh,q,n] = (Qcat . Kcat)/24, 128x128 block, K=192
// ============================================================
__global__ void __launch_bounds__(256, 2) mma_score(
    const float* __restrict__ qcat, const float* __restrict__ kcat,
    float* __restrict__ attn)
{
    extern __shared__ float sm[];
    float* Asb[2] = { sm, sm + 128*PITCH };
    float* Bsb[2] = { sm + 2*128*PITCH, sm + 3*128*PITCH };
    const int tid = threadIdx.x, lane = tid & 31, wid = tid >> 5;
    const int wm = wid & 1, wn = wid >> 1;
    const int g = lane >> 2, t = lane & 3;
    const int rA = ((lane >> 3) & 1)*8 + (lane & 7), cA = (lane >> 4)*4;
    const int rB = lane & 7, cB = ((lane >> 3) & 1)*4;
    const int bh = blockIdx.z;
    const int q0 = blockIdx.y * 128, n0 = blockIdx.x * 128;
    const float* Ab = qcat + (size_t)bh*NL*192 + (size_t)q0*192;
    const float* Bb = kcat + (size_t)bh*NL*192 + (size_t)n0*192;

    float acc[4][4][4] = {};

#define LOAD_STAGE_S(i, s) do {                                            \
        int k0 = (i) * 32;                                                 \
        _Pragma("unroll")                                                  \
        for (int it = 0; it < 4; it++) {                                   \
            int j = it*256 + tid;                                          \
            int r = j >> 3, c = j & 7;                                     \
            cpa16(s2u(Asb[s] + r*PITCH + c*4), Ab + (size_t)r*192 + k0 + c*4); \
            cpa16(s2u(Bsb[s] + r*PITCH + c*4), Bb + (size_t)r*192 + k0 + c*4); \
        }                                                                  \
        asm volatile("cp.async.commit_group;" ::: "memory");               \
    } while (0)

    LOAD_STAGE_S(0, 0);
    for (int i = 0; i < 6; i++) {
        int s = i & 1;
        if (i + 1 < 6) {
            LOAD_STAGE_S(i + 1, s ^ 1);
            asm volatile("cp.async.wait_group 1;" ::: "memory");
        } else {
            asm volatile("cp.async.wait_group 0;" ::: "memory");
        }
        __syncthreads();
        warp_mma<4,4>(Asb[s], Bsb[s], wm*64, wn*32, acc, rA, cA, rB, cB);
        __syncthreads();
    }
#undef LOAD_STAGE_S

    const float sc = 1.0f / 24.0f;
#pragma unroll
    for (int mi = 0; mi < 4; mi++)
#pragma unroll
        for (int ni = 0; ni < 4; ni++) {
            int mrow = q0 + wm*64 + mi*16 + g;
            int ncol = n0 + wn*32 + ni*8 + t*2;
            float* d0 = attn + ((size_t)bh*NL + mrow)*NL + ncol;
            float* d1 = attn + ((size_t)bh*NL + mrow + 8)*NL + ncol;
            *(float2*)d0 = make_float2(acc[mi][ni][0]*sc, acc[mi][ni][1]*sc);
            *(float2*)d1 = make_float2(acc[mi][ni][2]*sc, acc[mi][ni][3]*sc);
        }
}

// ============================================================
// mma_ctx: ctx[b,q,h*64+n] = sum_k attn[bh,q,k] * vt[bh,n,k]; 128x64, K=1024
// ============================================================
__global__ void __launch_bounds__(256, 2) mma_ctx(
    const float* __restrict__ attn, const float* __restrict__ vt, float* __restrict__ ctx)
{
    extern __shared__ float sm[];
    float* Asb[2] = { sm, sm + 128*PITCH };
    float* Bsb[2] = { sm + 2*128*PITCH, sm + 2*128*PITCH + 64*PITCH };
    const int tid = threadIdx.x, lane = tid & 31, wid = tid >> 5;
    const int wm = wid & 1, wn = wid >> 1;
    const int g = lane >> 2, t = lane & 3;
    const int rA = ((lane >> 3) & 1)*8 + (lane & 7), cA = (lane >> 4)*4;
    const int rB = lane & 7, cB = ((lane >> 3) & 1)*4;
    const int bh = blockIdx.y, q0 = blockIdx.x * 128;
    const float* Ab = attn + (size_t)bh*NL*NL + (size_t)q0*NL;
    const float* Bb = vt   + (size_t)bh*64*NL;

    float acc[4][2][4] = {};

#define LOAD_STAGE_C(i, s) do {                                            \
        int k0 = (i) * 32;                                                 \
        _Pragma("unroll")                                                  \
        for (int it = 0; it < 4; it++) {                                   \
            int j = it*256 + tid;                                          \
            int r = j >> 3, c = j & 7;                                     \
            cpa16(s2u(Asb[s] + r*PITCH + c*4), Ab + (size_t)r*NL + k0 + c*4); \
        }                                                                  \
        _Pragma("unroll")                                                  \
        for (int it = 0; it < 2; it++) {                                   \
            int j = it*256 + tid;                                          \
            int r = j >> 3, c = j & 7;                                     \
            cpa16(s2u(Bsb[s] + r*PITCH + c*4), Bb + (size_t)r*NL + k0 + c*4); \
        }                                                                  \
        asm volatile("cp.async.commit_group;" ::: "memory");               \
    } while (0)

    LOAD_STAGE_C(0, 0);
    for (int i = 0; i < 32; i++) {
        int s = i & 1;
        if (i + 1 < 32) {
            LOAD_STAGE_C(i + 1, s ^ 1);
            asm volatile("cp.async.wait_group 1;" ::: "memory");
        } else {
            asm volatile("cp.async.wait_group 0;" ::: "memory");
        }
        __syncthreads();
        warp_mma<4,2>(Asb[s], Bsb[s], wm*64, wn*16, acc, rA, cA, rB, cB);
        __syncthreads();
    }
#undef LOAD_STAGE_C

    const int b = bh >> 4, hh = bh & 15;
#pragma unroll
    for (int mi = 0; mi < 4; mi++)
#pragma unroll
        for (int ni = 0; ni < 2; ni++) {
            int mrow = q0 + wm*64 + mi*16 + g;
            int ncol = wn*16 + ni*8 + t*2;
            float v00 = rnd_tf32(acc[mi][ni][0]), v01 = rnd_tf32(acc[mi][ni][1]);
            float v10 = rnd_tf32(acc[mi][ni][2]), v11 = rnd_tf32(acc[mi][ni][3]);
            *(float2*)(ctx + ((size_t)(b*1024 + mrow))*1024 + hh*64 + ncol) = make_float2(v00, v01);
            *(float2*)(ctx + ((size_t)(b*1024 + mrow + 8))*1024 + hh*64 + ncol) = make_float2(v10, v11);
        }
}

// ============================================================
// transpose (+ tf32 round): dst[C,R] = src[R,C]^T, batch over z
// ============================================================
__global__ void __launch_bounds__(256) transpose_f32(
    const float* __restrict__ src, float* __restrict__ dst, int R, int C)
{
    __shared__ float tbuf[32][33];
    const int bx = blockIdx.x * 32, by = blockIdx.y * 32;
    const size_t base = (size_t)blockIdx.z * R * C;
    const int x = threadIdx.x, y0 = threadIdx.y;
#pragma unroll
    for (int dy = 0; dy < 32; dy += 8)
        tbuf[y0+dy][x] = src[base + (size_t)(by + y0 + dy)*C + bx + x];
    __syncthreads();
#pragma unroll
    for (int dy = 0; dy < 32; dy += 8)
        dst[base + (size_t)(bx + y0 + dy)*R + by + x] = rnd_tf32(tbuf[x][y0+dy]);
}

__global__ void __launch_bounds__(256) round_copy(
    const float4* __restrict__ in, float4* __restrict__ out)
{
    int i = blockIdx.x * 256 + threadIdx.x;
    float4 v = in[i];
    v.x = rnd_tf32(v.x); v.y = rnd_tf32(v.y);
    v.z = rnd_tf32(v.z); v.w = rnd_tf32(v.w);
    out[i] = v;
}

__global__ void __launch_bounds__(256) concat_bias(
    const float* __restrict__ a, const float* __restrict__ b,
    const float* __restrict__ c, float* __restrict__ o)
{
    int i = blockIdx.x * 256 + threadIdx.x;
    o[i] = (i < 1024) ? a[i] : (i < 2048) ? b[i - 1024] : c[i - 2048];
}

// ============================================================
// chord/bass features -> Kcat segments 1,2 (replicated over b)
// ============================================================
__global__ __launch_bounds__(256) void chordfeat(
    const int* __restrict__ pc, const int* __restrict__ bon,
    const float* __restrict__ Wc, const float* __restrict__ bc,
    const float* __restrict__ Wb, const float* __restrict__ bb,
    float* __restrict__ kcat)
{
    int idx = blockIdx.x * 256 + threadIdx.x;
    int l = idx >> 10, n = idx & 1023;
    float sc = bc[n], sb = bb[n];
#pragma unroll
    for (int p = 0; p < 12; p++) {
        sc += (float)pc[l*12 + p] * Wc[p*1024 + n];
        sb += (float)bon[l*12 + p] * Wb[p*1024 + n];
    }
    sc = rnd_tf32(sc); sb = rnd_tf32(sb);
    int h = n >> 6, hd = n & 63;
#pragma unroll
    for (int b = 0; b < 4; b++) {
        size_t row = ((size_t)((b*16 + h)*1024 + l))*192;
        kcat[row + 64 + hd]  = sc;
        kcat[row + 128 + hd] = sb;
    }
}

// ============================================================
// row softmax in place (+ round output for tf32 mma consumption)
// ============================================================
__global__ __launch_bounds__(256) void softmax_rows(float* __restrict__ attn)
{
    const size_t row = blockIdx.x;
    float4* p = (float4*)(attn + row * 1024);
    const int tid = threadIdx.x;
    float4 x = p[tid];
    __shared__ float smx[8];
    __shared__ float ssm[8];

    float m = fmaxf(fmaxf(x.x, x.y), fmaxf(x.z, x.w));
#pragma unroll
    for (int o = 16; o > 0; o >>= 1) m = fmaxf(m, __shfl_xor_sync(0xffffffffu, m, o));
    if ((tid & 31) == 0) smx[tid >> 5] = m;
    __syncthreads();
    m = smx[0];
#pragma unroll
    for (int i = 1; i < 8; i++) m = fmaxf(m, smx[i]);

    float e0 = __expf(x.x - m), e1 = __expf(x.y - m);
    float e2 = __expf(x.z - m), e3 = __expf(x.w - m);
    float s = e0 + e1 + e2 + e3;
#pragma unroll
    for (int o = 16; o > 0; o >>= 1) s += __shfl_xor_sync(0xffffffffu, s, o);
    if ((tid & 31) == 0) ssm[tid >> 5] = s;
    __syncthreads();
    s = ssm[0];
#pragma unroll
    for (int i = 1; i < 8; i++) s += ssm[i];

    float inv = 1.0f / s;
    p[tid] = make_float4(rnd_tf32(e0*inv), rnd_tf32(e1*inv),
                         rnd_tf32(e2*inv), rnd_tf32(e3*inv));
}

// ============================================================
// launch
// ============================================================
extern "C" void kernel_launch(void* const* d_in, const int* in_sizes, int n_in,
                              void* d_out, int out_size)
{
    const float* query = (const float*)d_in[0];
    const float* key   = (const float*)d_in[1];
    const float* value = (const float*)d_in[2];
    const int*   pc    = (const int*)d_in[3];
    const int*   bon   = (const int*)d_in[4];
    const float* Wpq = (const float*)d_in[5],  *bpq = (const float*)d_in[6];
    const float* Whq = (const float*)d_in[7],  *bhq = (const float*)d_in[8];
    const float* Wvq = (const float*)d_in[9],  *bvq = (const float*)d_in[10];
    const float* Wk  = (const float*)d_in[11], *bk  = (const float*)d_in[12];
    const float* Wv  = (const float*)d_in[13], *bv  = (const float*)d_in[14];
    const float* Wc  = (const float*)d_in[15], *bc  = (const float*)d_in[16];
    const float* Wb  = (const float*)d_in[17], *bb  = (const float*)d_in[18];
    const float* Wo  = (const float*)d_in[19], *bo  = (const float*)d_in[20];

    float *qcat_p, *kcat_p, *v_p, *vt_p, *ctx_p, *wt_p, *qr_p, *kr_p, *vr_p, *bcat_p;
    cudaGetSymbolAddress((void**)&qcat_p, g_qcat);
    cudaGetSymbolAddress((void**)&kcat_p, g_kcat);
    cudaGetSymbolAddress((void**)&v_p,    g_v);
    cudaGetSymbolAddress((void**)&vt_p,   g_vt);
    cudaGetSymbolAddress((void**)&ctx_p,  g_ctx);
    cudaGetSymbolAddress((void**)&wt_p,   g_wt);
    cudaGetSymbolAddress((void**)&qr_p,   g_qr);
    cudaGetSymbolAddress((void**)&kr_p,   g_kr);
    cudaGetSymbolAddress((void**)&vr_p,   g_vr);
    cudaGetSymbolAddress((void**)&bcat_p, g_bcat);

    float* WqcatT = wt_p;                       // [3072 x 1024]
    float* WkT    = wt_p + 3u*1024u*1024u;
    float* WvT    = wt_p + 4u*1024u*1024u;
    float* WoT    = wt_p + 5u*1024u*1024u;

    float* out  = (float*)d_out;
    float* attn = out + (size_t)NB * NL * ND;

    const int SM_BIG = 4 * 128 * PITCH * 4;                 // 73728
    const int SM_CTX = (2*128*PITCH + 2*64*PITCH) * 4;      // 55296
    cudaFuncSetAttribute(mma_gemm<LAY_QCAT,true>, cudaFuncAttributeMaxDynamicSharedMemorySize, SM_BIG);
    cudaFuncSetAttribute(mma_gemm<LAY_KCAT,true>, cudaFuncAttributeMaxDynamicSharedMemorySize, SM_BIG);
    cudaFuncSetAttribute(mma_gemm<LAY_HEAD,true>, cudaFuncAttributeMaxDynamicSharedMemorySize, SM_BIG);
    cudaFuncSetAttribute(mma_gemm<LAY_FLAT,false>,cudaFuncAttributeMaxDynamicSharedMemorySize, SM_BIG);
    cudaFuncSetAttribute(mma_score,               cudaFuncAttributeMaxDynamicSharedMemorySize, SM_BIG);
    cudaFuncSetAttribute(mma_ctx,                 cudaFuncAttributeMaxDynamicSharedMemorySize, SM_CTX);

    // tf32-round inputs
    round_copy<<<4096, 256>>>((const float4*)query, (float4*)qr_p);
    round_copy<<<4096, 256>>>((const float4*)key,   (float4*)kr_p);
    round_copy<<<4096, 256>>>((const float4*)value, (float4*)vr_p);

    // transpose + round weights (Q weights into one concatenated [3072,1024])
    dim3 tb(32, 8);
    transpose_f32<<<dim3(32, 32, 1), tb>>>(Wpq, WqcatT + 0u*1024u*1024u, 1024, 1024);
    transpose_f32<<<dim3(32, 32, 1), tb>>>(Whq, WqcatT + 1u*1024u*1024u, 1024, 1024);
    transpose_f32<<<dim3(32, 32, 1), tb>>>(Wvq, WqcatT + 2u*1024u*1024u, 1024, 1024);
    transpose_f32<<<dim3(32, 32, 1), tb>>>(Wk,  WkT, 1024, 1024);
    transpose_f32<<<dim3(32, 32, 1), tb>>>(Wv,  WvT, 1024, 1024);
    transpose_f32<<<dim3(32, 32, 1), tb>>>(Wo,  WoT, 1024, 1024);
    concat_bias<<<12, 256>>>(bpq, bhq, bvq, bcat_p);

    // projections
    mma_gemm<LAY_QCAT,true><<<dim3(24, 32), 256, SM_BIG>>>(qr_p, WqcatT, bcat_p, qcat_p);
    mma_gemm<LAY_KCAT,true><<<dim3(8, 32),  256, SM_BIG>>>(kr_p, WkT, bk, kcat_p);
    mma_gemm<LAY_HEAD,true><<<dim3(8, 32),  256, SM_BIG>>>(vr_p, WvT, bv, v_p);

    transpose_f32<<<dim3(2, 32, NBH), tb>>>(v_p, vt_p, 1024, 64);   // vt[bh][hd][l]
    chordfeat<<<4096, 256>>>(pc, bon, Wc, bc, Wb, bb, kcat_p);

    mma_score<<<dim3(8, 8, NBH), 256, SM_BIG>>>(qcat_p, kcat_p, attn);
    softmax_rows<<<NBH * NL, 256>>>(attn);
    mma_ctx<<<dim3(8, NBH), 256, SM_CTX>>>(attn, vt_p, ctx_p);
    mma_gemm<LAY_FLAT,false><<<dim3(8, 32), 256, SM_BIG>>>(ctx_p, WoT, bo, out);
}

// round 5
// speedup vs baseline: 3.5828x; 1.0465x over previous
#include <cuda_runtime.h>
#include <math.h>
#include <cstdint>

#define NB 4
#define NL 1024
#define ND 1024
#define NH 16
#define NHD 64
#define NBH (NB*NH)

// ---------------- scratch (device globals) ----------------
__device__ __align__(16) float g_qcat[NBH*NL*192];     // [bh][l][pq|hq|vq]
__device__ __align__(16) float g_kcat[NBH*NL*192];     // [bh][l][k|cf|bf]
__device__ __align__(16) float g_v [NBH*NL*NHD];
__device__ __align__(16) float g_vt[NBH*NL*NHD];
__device__ __align__(16) float g_ctx[NB*NL*ND];
__device__ __align__(16) float g_wt[6u*1024u*1024u];   // transposed (+tf32-rounded) weights
__device__ __align__(16) float g_bcat[3072];
__device__ __align__(16) float g_pmax[NBH*NL*8];       // per-(row, n-tile) partial max
__device__ __align__(16) float g_psum[NBH*NL*8];       // per-(row, n-tile) partial sumexp
__device__ __align__(16) float g_rowm[NBH*NL];         // global row max
__device__ __align__(16) float g_rowi[NBH*NL];         // 1 / global row sum

// ---------------- helpers ----------------
__device__ __forceinline__ float rnd_tf32(float x) {
    uint32_t u;
    asm("cvt.rna.tf32.f32 %0, %1;" : "=r"(u) : "f"(x));
    return __uint_as_float(u);
}
__device__ __forceinline__ uint32_t rnd_tf32_u(uint32_t x) {
    uint32_t u;
    asm("cvt.rna.tf32.f32 %0, %1;" : "=r"(u) : "f"(__uint_as_float(x)));
    return u;
}
__device__ __forceinline__ void cpa16(uint32_t s, const void* g) {
    asm volatile("cp.async.cg.shared.global [%0], [%1], 16;" :: "r"(s), "l"(g) : "memory");
}
__device__ __forceinline__ uint32_t s2u(const void* p) {
    return (uint32_t)__cvta_generic_to_shared(p);
}
__device__ __forceinline__ void ldsm4(uint32_t (&r)[4], uint32_t a) {
    asm volatile("ldmatrix.sync.aligned.m8n8.x4.shared.b16 {%0,%1,%2,%3}, [%4];"
        : "=r"(r[0]), "=r"(r[1]), "=r"(r[2]), "=r"(r[3]) : "r"(a));
}
__device__ __forceinline__ void ldsm2(uint32_t (&r)[2], uint32_t a) {
    asm volatile("ldmatrix.sync.aligned.m8n8.x2.shared.b16 {%0,%1}, [%2];"
        : "=r"(r[0]), "=r"(r[1]) : "r"(a));
}

#define PITCH 36   // floats; rows stride 144B -> 16B aligned, ldmatrix conflict-free

// warp-level tf32 mma over one BK=32 stage; fragments via ldmatrix.
// RA: round A fragments to tf32 (RNA) after load (for raw fp32 A inputs).
template<int MSUB, int NSUB, bool RA>
__device__ __forceinline__ void warp_mma(
    const float* __restrict__ As, const float* __restrict__ Bs,
    int mrow0, int ncol0, float (&acc)[MSUB][NSUB][4],
    int rA, int cA, int rB, int cB)
{
#pragma unroll
    for (int k8 = 0; k8 < 4; k8++) {
        uint32_t a[MSUB][4];
#pragma unroll
        for (int mi = 0; mi < MSUB; mi++) {
            ldsm4(a[mi], s2u(As + (mrow0 + mi*16 + rA)*PITCH + k8*8 + cA));
            if (RA) {
#pragma unroll
                for (int q = 0; q < 4; q++) a[mi][q] = rnd_tf32_u(a[mi][q]);
            }
        }
        uint32_t b[NSUB][2];
#pragma unroll
        for (int ni = 0; ni < NSUB; ni++)
            ldsm2(b[ni], s2u(Bs + (ncol0 + ni*8 + rB)*PITCH + k8*8 + cB));
#pragma unroll
        for (int mi = 0; mi < MSUB; mi++)
#pragma unroll
            for (int ni = 0; ni < NSUB; ni++) {
                asm volatile(
                    "mma.sync.aligned.m16n8k8.row.col.f32.tf32.tf32.f32 "
                    "{%0,%1,%2,%3}, {%4,%5,%6,%7}, {%8,%9}, {%0,%1,%2,%3};"
                    : "+f"(acc[mi][ni][0]), "+f"(acc[mi][ni][1]),
                      "+f"(acc[mi][ni][2]), "+f"(acc[mi][ni][3])
                    : "r"(a[mi][0]), "r"(a[mi][1]), "r"(a[mi][2]), "r"(a[mi][3]),
                      "r"(b[ni][0]), "r"(b[ni][1]));
            }
    }
}

// output layouts
#define LAY_FLAT 0   // C[m][1024]
#define LAY_HEAD 1   // C[bh][l][64]          (N=1024)
#define LAY_QCAT 2   // Qcat[bh][l][192], seg = n>>10  (N=3072)
#define LAY_KCAT 3   // Kcat[bh][l][192], seg 0        (N=1024)

template<int LAYOUT>
__device__ __forceinline__ float* out_addr(float* C, int mrow, int ncol) {
    if (LAYOUT == LAY_FLAT) return C + (size_t)mrow*1024 + ncol;
    int b = mrow >> 10, l = mrow & 1023;
    if (LAYOUT == LAY_HEAD) {
        int h = ncol >> 6, hd = ncol & 63;
        return C + ((size_t)((b*16 + h)*1024 + l))*64 + hd;
    }
    if (LAYOUT == LAY_QCAT) {
        int seg = ncol >> 10, nn = ncol & 1023;
        int h = nn >> 6, hd = nn & 63;
        return C + ((size_t)((b*16 + h)*1024 + l))*192 + seg*64 + hd;
    }
    int h = ncol >> 6, hd = ncol & 63;
    return C + ((size_t)((b*16 + h)*1024 + l))*192 + hd;
}

// ============================================================
// mma_gemm: C = A[4096x1024] @ BT^T + bias, BT=[N,K]
// 128x128 block, BK=32, 8 warps (2m x 4n)
// ============================================================
template<int LAYOUT, bool ROUND, bool RA>
__global__ void __launch_bounds__(256, 2) mma_gemm(
    const float* __restrict__ A, const float* __restrict__ BT,
    const float* __restrict__ bias, float* __restrict__ C)
{
    extern __shared__ float sm[];
    float* Asb[2] = { sm, sm + 128*PITCH };
    float* Bsb[2] = { sm + 2*128*PITCH, sm + 3*128*PITCH };
    const int tid = threadIdx.x, lane = tid & 31, wid = tid >> 5;
    const int wm = wid & 1, wn = wid >> 1;
    const int g = lane >> 2, t = lane & 3;
    const int rA = ((lane >> 3) & 1)*8 + (lane & 7), cA = (lane >> 4)*4;
    const int rB = lane & 7, cB = ((lane >> 3) & 1)*4;
    const int m0 = blockIdx.y * 128, n0 = blockIdx.x * 128;

    float acc[4][4][4] = {};

#define LOAD_STAGE(i, s) do {                                              \
        int k0 = (i) * 32;                                                 \
        _Pragma("unroll")                                                  \
        for (int it = 0; it < 4; it++) {                                   \
            int j = it*256 + tid;                                          \
            int r = j >> 3, c = j & 7;                                     \
            cpa16(s2u(Asb[s] + r*PITCH + c*4), A  + (size_t)(m0+r)*1024 + k0 + c*4); \
            cpa16(s2u(Bsb[s] + r*PITCH + c*4), BT + (size_t)(n0+r)*1024 + k0 + c*4); \
        }                                                                  \
        asm volatile("cp.async.commit_group;" ::: "memory");               \
    } while (0)

    LOAD_STAGE(0, 0);
    for (int i = 0; i < 32; i++) {
        int s = i & 1;
        if (i + 1 < 32) {
            LOAD_STAGE(i + 1, s ^ 1);
            asm volatile("cp.async.wait_group 1;" ::: "memory");
        } else {
            asm volatile("cp.async.wait_group 0;" ::: "memory");
        }
        __syncthreads();
        warp_mma<4,4,RA>(Asb[s], Bsb[s], wm*64, wn*32, acc, rA, cA, rB, cB);
        __syncthreads();
    }
#undef LOAD_STAGE

#pragma unroll
    for (int mi = 0; mi < 4; mi++)
#pragma unroll
        for (int ni = 0; ni < 4; ni++) {
            int mrow = m0 + wm*64 + mi*16 + g;
            int ncol = n0 + wn*32 + ni*8 + t*2;
            float b0 = bias[ncol], b1 = bias[ncol+1];
            float v00 = acc[mi][ni][0] + b0, v01 = acc[mi][ni][1] + b1;
            float v10 = acc[mi][ni][2] + b0, v11 = acc[mi][ni][3] + b1;
            if (ROUND) { v00 = rnd_tf32(v00); v01 = rnd_tf32(v01);
                         v10 = rnd_tf32(v10); v11 = rnd_tf32(v11); }
            *(float2*)out_addr<LAYOUT>(C, mrow,     ncol) = make_float2(v00, v01);
            *(float2*)out_addr<LAYOUT>(C, mrow + 8, ncol) = make_float2(v10, v11);
        }
}

// ============================================================
// mma_score: raw scaled scores -> attn buffer, + per-tile row partials
// S[bh,q,n] = (Qcat . Kcat)/24, 128x128 block, K=192
// ============================================================
__global__ void __launch_bounds__(256, 2) mma_score(
    const float* __restrict__ qcat, const float* __restrict__ kcat,
    float* __restrict__ attn, float* __restrict__ pmax, float* __restrict__ psum)
{
    extern __shared__ float sm[];
    float* Asb[2] = { sm, sm + 128*PITCH };
    float* Bsb[2] = { sm + 2*128*PITCH, sm + 3*128*PITCH };
    const int tid = threadIdx.x, lane = tid & 31, wid = tid >> 5;
    const int wm = wid & 1, wn = wid >> 1;
    const int g = lane >> 2, t = lane & 3;
    const int rA = ((lane >> 3) & 1)*8 + (lane & 7), cA = (lane >> 4)*4;
    const int rB = lane & 7, cB = ((lane >> 3) & 1)*4;
    const int bh = blockIdx.z;
    const int q0 = blockIdx.y * 128, n0 = blockIdx.x * 128;
    const float* Ab = qcat + (size_t)bh*NL*192 + (size_t)q0*192;
    const float* Bb = kcat + (size_t)bh*NL*192 + (size_t)n0*192;

    float acc[4][4][4] = {};

#define LOAD_STAGE_S(i, s) do {                                            \
        int k0 = (i) * 32;                                                 \
        _Pragma("unroll")                                                  \
        for (int it = 0; it < 4; it++) {                                   \
            int j = it*256 + tid;                                          \
            int r = j >> 3, c = j & 7;                                     \
            cpa16(s2u(Asb[s] + r*PITCH + c*4), Ab + (size_t)r*192 + k0 + c*4); \
            cpa16(s2u(Bsb[s] + r*PITCH + c*4), Bb + (size_t)r*192 + k0 + c*4); \
        }                                                                  \
        asm volatile("cp.async.commit_group;" ::: "memory");               \
    } while (0)

    LOAD_STAGE_S(0, 0);
    for (int i = 0; i < 6; i++) {
        int s = i & 1;
        if (i + 1 < 6) {
            LOAD_STAGE_S(i + 1, s ^ 1);
            asm volatile("cp.async.wait_group 1;" ::: "memory");
        } else {
            asm volatile("cp.async.wait_group 0;" ::: "memory");
        }
        __syncthreads();
        warp_mma<4,4,false>(Asb[s], Bsb[s], wm*64, wn*32, acc, rA, cA, rB, cB);
        __syncthreads();
    }
#undef LOAD_STAGE_S

    const float sc = 1.0f / 24.0f;
    // raw scaled score stores
#pragma unroll
    for (int mi = 0; mi < 4; mi++)
#pragma unroll
        for (int ni = 0; ni < 4; ni++) {
            int mrow = q0 + wm*64 + mi*16 + g;
            int ncol = n0 + wn*32 + ni*8 + t*2;
            float* d0 = attn + ((size_t)bh*NL + mrow)*NL + ncol;
            float* d1 = attn + ((size_t)bh*NL + mrow + 8)*NL + ncol;
            *(float2*)d0 = make_float2(acc[mi][ni][0]*sc, acc[mi][ni][1]*sc);
            *(float2*)d1 = make_float2(acc[mi][ni][2]*sc, acc[mi][ni][3]*sc);
        }

    // per-row partial max / sumexp over this 128-col tile
    float* pm = sm;          // [128][4]
    float* ps = sm + 512;    // [128][4]
#pragma unroll
    for (int mi = 0; mi < 4; mi++)
#pragma unroll
        for (int half = 0; half < 2; half++) {
            float v[8];
#pragma unroll
            for (int ni = 0; ni < 4; ni++) {
                v[ni*2+0] = acc[mi][ni][half*2+0] * sc;
                v[ni*2+1] = acc[mi][ni][half*2+1] * sc;
            }
            float mx = v[0];
#pragma unroll
            for (int q = 1; q < 8; q++) mx = fmaxf(mx, v[q]);
            mx = fmaxf(mx, __shfl_xor_sync(0xffffffffu, mx, 1));
            mx = fmaxf(mx, __shfl_xor_sync(0xffffffffu, mx, 2));
            float se = 0.f;
#pragma unroll
            for (int q = 0; q < 8; q++) se += __expf(v[q] - mx);
            se += __shfl_xor_sync(0xffffffffu, se, 1);
            se += __shfl_xor_sync(0xffffffffu, se, 2);
            if (t == 0) {
                int lr = wm*64 + mi*16 + half*8 + g;
                pm[lr*4 + wn] = mx;
                ps[lr*4 + wn] = se;
            }
        }
    __syncthreads();
    if (tid < 128) {
        int lr = tid;
        float M = pm[lr*4];
#pragma unroll
        for (int q = 1; q < 4; q++) M = fmaxf(M, pm[lr*4+q]);
        float S = 0.f;
#pragma unroll
        for (int q = 0; q < 4; q++) S += ps[lr*4+q] * __expf(pm[lr*4+q] - M);
        size_t row = (size_t)bh*NL + q0 + lr;
        pmax[row*8 + blockIdx.x] = M;
        psum[row*8 + blockIdx.x] = S;
    }
}

// ============================================================
// combine_rows: global row max + 1/sum from 8 tile partials
// ============================================================
__global__ void __launch_bounds__(256) combine_rows(
    const float* __restrict__ pmax, const float* __restrict__ psum,
    float* __restrict__ rowm, float* __restrict__ rowi)
{
    int row = blockIdx.x * 256 + threadIdx.x;
    const float* pmr = pmax + (size_t)row*8;
    const float* psr = psum + (size_t)row*8;
    float M = pmr[0];
#pragma unroll
    for (int q = 1; q < 8; q++) M = fmaxf(M, pmr[q]);
    float S = 0.f;
#pragma unroll
    for (int q = 0; q < 8; q++) S += psr[q] * __expf(pmr[q] - M);
    rowm[row] = M;
    rowi[row] = 1.0f / S;
}

// ============================================================
// mma_ctx: fused softmax-apply + PV gemm.
// Reads raw scores from attn, writes normalized attn IN PLACE,
// ctx[b,q,h*64+n] = sum_k p[q,k] * vt[bh,n,k]; 128x64, K=1024
// ============================================================
__global__ void __launch_bounds__(256, 2) mma_ctx(
    float* __restrict__ attn, const float* __restrict__ vt,
    const float* __restrict__ rowm, const float* __restrict__ rowi,
    float* __restrict__ ctx)
{
    extern __shared__ float sm[];
    float* Asb[2] = { sm, sm + 128*PITCH };
    float* Bsb[2] = { sm + 2*128*PITCH, sm + 2*128*PITCH + 64*PITCH };
    float* rowM = sm + 2*128*PITCH + 2*64*PITCH;
    float* rowI = rowM + 128;
    const int tid = threadIdx.x, lane = tid & 31, wid = tid >> 5;
    const int wm = wid & 1, wn = wid >> 1;
    const int g = lane >> 2, t = lane & 3;
    const int rA = ((lane >> 3) & 1)*8 + (lane & 7), cA = (lane >> 4)*4;
    const int rB = lane & 7, cB = ((lane >> 3) & 1)*4;
    const int bh = blockIdx.y, q0 = blockIdx.x * 128;
    float* Ab = attn + (size_t)bh*NL*NL + (size_t)q0*NL;
    const float* Bb = vt + (size_t)bh*64*NL;

    if (tid < 128) {
        rowM[tid] = rowm[(size_t)bh*NL + q0 + tid];
        rowI[tid] = rowi[(size_t)bh*NL + q0 + tid];
    }

    float acc[4][2][4] = {};

#define LOAD_STAGE_C(i, s) do {                                            \
        int k0 = (i) * 32;                                                 \
        _Pragma("unroll")                                                  \
        for (int it = 0; it < 4; it++) {                                   \
            int j = it*256 + tid;                                          \
            int r = j >> 3, c = j & 7;                                     \
            cpa16(s2u(Asb[s] + r*PITCH + c*4), Ab + (size_t)r*NL + k0 + c*4); \
        }                                                                  \
        _Pragma("unroll")                                                  \
        for (int it = 0; it < 2; it++) {                                   \
            int j = it*256 + tid;                                          \
            int r = j >> 3, c = j & 7;                                     \
            cpa16(s2u(Bsb[s] + r*PITCH + c*4), Bb + (size_t)r*NL + k0 + c*4); \
        }                                                                  \
        asm volatile("cp.async.commit_group;" ::: "memory");               \
    } while (0)

    LOAD_STAGE_C(0, 0);
    for (int i = 0; i < 32; i++) {
        int s = i & 1;
        if (i + 1 < 32) {
            LOAD_STAGE_C(i + 1, s ^ 1);
            asm volatile("cp.async.wait_group 1;" ::: "memory");
        } else {
            asm volatile("cp.async.wait_group 0;" ::: "memory");
        }
        __syncthreads();
        // softmax transform on this 128x32 score chunk, in smem; write attn back
        {
            int k0 = i * 32;
#pragma unroll
            for (int it = 0; it < 4; it++) {
                int j = it*256 + tid;
                int r = j >> 3, c4 = j & 7;
                float4* ap = (float4*)(Asb[s] + r*PITCH + c4*4);
                float4 v = *ap;
                float M = rowM[r], I = rowI[r];
                v.x = rnd_tf32(__expf(v.x - M) * I);
                v.y = rnd_tf32(__expf(v.y - M) * I);
                v.z = rnd_tf32(__expf(v.z - M) * I);
                v.w = rnd_tf32(__expf(v.w - M) * I);
                *ap = v;
                *(float4*)(Ab + (size_t)r*NL + k0 + c4*4) = v;
            }
        }
        __syncthreads();
        warp_mma<4,2,false>(Asb[s], Bsb[s], wm*64, wn*16, acc, rA, cA, rB, cB);
        __syncthreads();
    }
#undef LOAD_STAGE_C

    const int b = bh >> 4, hh = bh & 15;
#pragma unroll
    for (int mi = 0; mi < 4; mi++)
#pragma unroll
        for (int ni = 0; ni < 2; ni++) {
            int mrow = q0 + wm*64 + mi*16 + g;
            int ncol = wn*16 + ni*8 + t*2;
            float v00 = rnd_tf32(acc[mi][ni][0]), v01 = rnd_tf32(acc[mi][ni][1]);
            float v10 = rnd_tf32(acc[mi][ni][2]), v11 = rnd_tf32(acc[mi][ni][3]);
            *(float2*)(ctx + ((size_t)(b*1024 + mrow))*1024 + hh*64 + ncol) = make_float2(v00, v01);
            *(float2*)(ctx + ((size_t)(b*1024 + mrow + 8))*1024 + hh*64 + ncol) = make_float2(v10, v11);
        }
}

// ============================================================
// transpose (+ tf32 round): dst[C,R] = src[R,C]^T, batch over z
// ============================================================
__global__ void __launch_bounds__(256) transpose_f32(
    const float* __restrict__ src, float* __restrict__ dst, int R, int C)
{
    __shared__ float tbuf[32][33];
    const int bx = blockIdx.x * 32, by = blockIdx.y * 32;
    const size_t base = (size_t)blockIdx.z * R * C;
    const int x = threadIdx.x, y0 = threadIdx.y;
#pragma unroll
    for (int dy = 0; dy < 32; dy += 8)
        tbuf[y0+dy][x] = src[base + (size_t)(by + y0 + dy)*C + bx + x];
    __syncthreads();
#pragma unroll
    for (int dy = 0; dy < 32; dy += 8)
        dst[base + (size_t)(bx + y0 + dy)*R + by + x] = rnd_tf32(tbuf[x][y0+dy]);
}

__global__ void __launch_bounds__(256) concat_bias(
    const float* __restrict__ a, const float* __restrict__ b,
    const float* __restrict__ c, float* __restrict__ o)
{
    int i = blockIdx.x * 256 + threadIdx.x;
    o[i] = (i < 1024) ? a[i] : (i < 2048) ? b[i - 1024] : c[i - 2048];
}

// ============================================================
// chord/bass features -> Kcat segments 1,2 (replicated over b)
// ============================================================
__global__ __launch_bounds__(256) void chordfeat(
    const int* __restrict__ pc, const int* __restrict__ bon,
    const float* __restrict__ Wc, const float* __restrict__ bc,
    const float* __restrict__ Wb, const float* __restrict__ bb,
    float* __restrict__ kcat)
{
    int idx = blockIdx.x * 256 + threadIdx.x;
    int l = idx >> 10, n = idx & 1023;
    float sc = bc[n], sb = bb[n];
#pragma unroll
    for (int p = 0; p < 12; p++) {
        sc += (float)pc[l*12 + p] * Wc[p*1024 + n];
        sb += (float)bon[l*12 + p] * Wb[p*1024 + n];
    }
    sc = rnd_tf32(sc); sb = rnd_tf32(sb);
    int h = n >> 6, hd = n & 63;
#pragma unroll
    for (int b = 0; b < 4; b++) {
        size_t row = ((size_t)((b*16 + h)*1024 + l))*192;
        kcat[row + 64 + hd]  = sc;
        kcat[row + 128 + hd] = sb;
    }
}

// ============================================================
// launch
// ============================================================
extern "C" void kernel_launch(void* const* d_in, const int* in_sizes, int n_in,
                              void* d_out, int out_size)
{
    const float* query = (const float*)d_in[0];
    const float* key   = (const float*)d_in[1];
    const float* value = (const float*)d_in[2];
    const int*   pc    = (const int*)d_in[3];
    const int*   bon   = (const int*)d_in[4];
    const float* Wpq = (const float*)d_in[5],  *bpq = (const float*)d_in[6];
    const float* Whq = (const float*)d_in[7],  *bhq = (const float*)d_in[8];
    const float* Wvq = (const float*)d_in[9],  *bvq = (const float*)d_in[10];
    const float* Wk  = (const float*)d_in[11], *bk  = (const float*)d_in[12];
    const float* Wv  = (const float*)d_in[13], *bv  = (const float*)d_in[14];
    const float* Wc  = (const float*)d_in[15], *bc  = (const float*)d_in[16];
    const float* Wb  = (const float*)d_in[17], *bb  = (const float*)d_in[18];
    const float* Wo  = (const float*)d_in[19], *bo  = (const float*)d_in[20];

    float *qcat_p, *kcat_p, *v_p, *vt_p, *ctx_p, *wt_p, *bcat_p;
    float *pmax_p, *psum_p, *rowm_p, *rowi_p;
    cudaGetSymbolAddress((void**)&qcat_p, g_qcat);
    cudaGetSymbolAddress((void**)&kcat_p, g_kcat);
    cudaGetSymbolAddress((void**)&v_p,    g_v);
    cudaGetSymbolAddress((void**)&vt_p,   g_vt);
    cudaGetSymbolAddress((void**)&ctx_p,  g_ctx);
    cudaGetSymbolAddress((void**)&wt_p,   g_wt);
    cudaGetSymbolAddress((void**)&bcat_p, g_bcat);
    cudaGetSymbolAddress((void**)&pmax_p, g_pmax);
    cudaGetSymbolAddress((void**)&psum_p, g_psum);
    cudaGetSymbolAddress((void**)&rowm_p, g_rowm);
    cudaGetSymbolAddress((void**)&rowi_p, g_rowi);

    float* WqcatT = wt_p;                       // [3072 x 1024]
    float* WkT    = wt_p + 3u*1024u*1024u;
    float* WvT    = wt_p + 4u*1024u*1024u;
    float* WoT    = wt_p + 5u*1024u*1024u;

    float* out  = (float*)d_out;
    float* attn = out + (size_t)NB * NL * ND;

    const int SM_BIG = 4 * 128 * PITCH * 4;                        // 73728
    const int SM_CTX = (2*128*PITCH + 2*64*PITCH + 256) * 4;       // 56320
    cudaFuncSetAttribute(mma_gemm<LAY_QCAT,true,true>,  cudaFuncAttributeMaxDynamicSharedMemorySize, SM_BIG);
    cudaFuncSetAttribute(mma_gemm<LAY_KCAT,true,true>,  cudaFuncAttributeMaxDynamicSharedMemorySize, SM_BIG);
    cudaFuncSetAttribute(mma_gemm<LAY_HEAD,true,true>,  cudaFuncAttributeMaxDynamicSharedMemorySize, SM_BIG);
    cudaFuncSetAttribute(mma_gemm<LAY_FLAT,false,false>,cudaFuncAttributeMaxDynamicSharedMemorySize, SM_BIG);
    cudaFuncSetAttribute(mma_score,                     cudaFuncAttributeMaxDynamicSharedMemorySize, SM_BIG);
    cudaFuncSetAttribute(mma_ctx,                       cudaFuncAttributeMaxDynamicSharedMemorySize, SM_CTX);

    // transpose + round weights (Q weights into one concatenated [3072,1024])
    dim3 tb(32, 8);
    transpose_f32<<<dim3(32, 32, 1), tb>>>(Wpq, WqcatT + 0u*1024u*1024u, 1024, 1024);
    transpose_f32<<<dim3(32, 32, 1), tb>>>(Whq, WqcatT + 1u*1024u*1024u, 1024, 1024);
    transpose_f32<<<dim3(32, 32, 1), tb>>>(Wvq, WqcatT + 2u*1024u*1024u, 1024, 1024);
    transpose_f32<<<dim3(32, 32, 1), tb>>>(Wk,  WkT, 1024, 1024);
    transpose_f32<<<dim3(32, 32, 1), tb>>>(Wv,  WvT, 1024, 1024);
    transpose_f32<<<dim3(32, 32, 1), tb>>>(Wo,  WoT, 1024, 1024);
    concat_bias<<<12, 256>>>(bpq, bhq, bvq, bcat_p);

    // projections (A-fragment rounding fused; raw inputs consumed directly)
    mma_gemm<LAY_QCAT,true,true><<<dim3(24, 32), 256, SM_BIG>>>(query, WqcatT, bcat_p, qcat_p);
    mma_gemm<LAY_KCAT,true,true><<<dim3(8, 32),  256, SM_BIG>>>(key,   WkT, bk, kcat_p);
    mma_gemm<LAY_HEAD,true,true><<<dim3(8, 32),  256, SM_BIG>>>(value, WvT, bv, v_p);

    transpose_f32<<<dim3(2, 32, NBH), tb>>>(v_p, vt_p, 1024, 64);   // vt[bh][hd][l]
    chordfeat<<<4096, 256>>>(pc, bon, Wc, bc, Wb, bb, kcat_p);

    mma_score<<<dim3(8, 8, NBH), 256, SM_BIG>>>(qcat_p, kcat_p, attn, pmax_p, psum_p);
    combine_rows<<<NBH*NL/256, 256>>>(pmax_p, psum_p, rowm_p, rowi_p);
    mma_ctx<<<dim3(8, NBH), 256, SM_CTX>>>(attn, vt_p, rowm_p, rowi_p, ctx_p);
    mma_gemm<LAY_FLAT,false,false><<<dim3(8, 32), 256, SM_BIG>>>(ctx_p, WoT, bo, out);
}